// round 16
// baseline (speedup 1.0000x reference)
#include <cuda_runtime.h>
#include <cuda_bf16.h>
#include <cstdint>

// Problem constants (fixed by setup_inputs)
#define BATCH   16
#define IMG_H   192
#define IMG_W   640
#define HW      (IMG_H * IMG_W)       // 122880
#define XS      240                   // W*3/8
#define XE      400                   // W*5/8
#define PRIOR_W (XE - XS)             // 160
#define NPRIOR  15360                 // (192-96)*160
#define ITERS   200
#define KMED    ((NPRIOR - 1) / 2)    // 7679, torch lower-median index
#define NH      8                     // hypotheses per ransac block (fits regs)
#define RNB     (ITERS / NH)          // 25 ransac blocks per batch
#define NSPLIT  8                     // median blocks per batch (co-resident)
#define SEG     (NPRIOR / NSPLIT)     // 1920 elements per median block
#define NBINS   2048

// Scratch (static device globals — no allocation)
__device__ float4   g_prior[BATCH * NPRIOR];    // packed prior points (x,y,z,0)
__device__ float    g_prior_y[BATCH * NPRIOR];  // y channel contiguous
__device__ float    g_thr[BATCH];
__device__ unsigned g_best[BATCH];              // (count<<8) | (199-iter)
__device__ unsigned g_done[BATCH];              // ransac tickets (self-resetting)
__device__ float4   g_plane[BATCH];             // winning plane per batch
__device__ unsigned g_hist[6][BATCH][NBINS];    // one hist per (mode,pass); pre-zeroed
__device__ unsigned g_arrive[BATCH][6];         // median spin-barrier counters

// ---------------------------------------------------------------------------
// order-preserving float <-> uint key
// ---------------------------------------------------------------------------
__device__ __forceinline__ unsigned fkey(float f) {
    unsigned u = __float_as_uint(f);
    return (u & 0x80000000u) ? ~u : (u | 0x80000000u);
}
__device__ __forceinline__ float kfloat(unsigned k) {
    unsigned u = (k & 0x80000000u) ? (k ^ 0x80000000u) : ~k;
    return __uint_as_float(u);
}

// ---------------------------------------------------------------------------
// Kernel 1: pack prior crop (full chip); zero g_best + median hists/counters
// ---------------------------------------------------------------------------
__global__ void pack_kernel(const float* __restrict__ pt,
                            const float* __restrict__ Kmat) {
    int idx = blockIdx.x * blockDim.x + threadIdx.x;
    unsigned* hflat = &g_hist[0][0][0];
    if (idx < 6 * BATCH * NBINS) hflat[idx] = 0u;
    if (idx < BATCH * 6) (&g_arrive[0][0])[idx] = 0u;
    if (idx < BATCH) g_best[idx] = 0u;
    if (idx >= BATCH * NPRIOR) return;
    int b = idx / NPRIOR;
    int n = idx - b * NPRIOR;
    int ys = (int)Kmat[b * 9 + 5];            // K[b,1,2] -> 96
    int r = n / PRIOR_W;
    int c = n - r * PRIOR_W;
    long base = (long)b * 3 * HW + (long)(ys + r) * IMG_W + XS + c;
    float x = pt[base];
    float y = pt[base + HW];
    float z = pt[base + 2 * HW];
    g_prior[idx]   = make_float4(x, y, z, 0.0f);
    g_prior_y[idx] = y;
}

// ---------------------------------------------------------------------------
// Kernel 2: exact lower-medians via 3-pass (11/11/10-bit) radix select,
// PARALLELIZED 8 blocks per batch (co-resident spin-sync, global hists).
//   med = median_low(y);  thr = median_low(|med - y|)
// grid = (NSPLIT, BATCH) = (8,16), block = 256. Keys register-resident.
// Per pass: local atomics into pre-zeroed g_hist[gp][b] -> threadfence ->
// arrival counter -> tid0 nanosleep-spin until 8 arrivals -> every block
// redundantly scans the 2048 bins (deterministic identical selection).
// ---------------------------------------------------------------------------
__global__ void __launch_bounds__(256) median_kernel() {
    __shared__ unsigned s_wsum[8];
    __shared__ unsigned s_woff[8];
    __shared__ unsigned s_sel[2];

    const int b     = blockIdx.y;
    const int split = blockIdx.x;
    const int tid   = threadIdx.x;
    const int lane  = tid & 31;
    const int w     = tid >> 5;
    const int base  = b * NPRIOR + split * SEG;
    const bool v7   = (tid < SEG - 7 * 256);   // j==7 element validity (tid<128)

    // load this block's 1920 keys into registers (8 per thread)
    unsigned key[8];
    #pragma unroll
    for (int j = 0; j < 8; j++) {
        int idx = tid + j * 256;
        key[j] = (idx < SEG) ? fkey(g_prior_y[base + idx]) : 0u;
    }

    const int SHIFT[3]      = {21, 10, 0};     // digit start bit
    const unsigned DMASK[3] = {0x7FFu, 0x7FFu, 0x3FFu};
    const int HI[3]         = {32, 21, 10};    // resolved-prefix boundary

    for (int mode = 0; mode < 2; mode++) {
        unsigned pref = 0u;
        unsigned kk   = KMED;

        for (int pass = 0; pass < 3; pass++) {
            const int gp = mode * 3 + pass;
            const int shift = SHIFT[pass];
            const unsigned dmask = DMASK[pass];
            const int hi = HI[pass];
            unsigned* __restrict__ hist = &g_hist[gp][b][0];

            // histogram this block's elements matching the resolved prefix
            #pragma unroll
            for (int j = 0; j < 8; j++) {
                if (j == 7 && !v7) break;
                unsigned kj = key[j];
                bool ok = (pass == 0) || ((kj >> hi) == (pref >> hi));
                if (ok) atomicAdd(&hist[(kj >> shift) & dmask], 1u);
            }

            // cross-block barrier for this batch
            __threadfence();
            __syncthreads();
            if (tid == 0) {
                atomicAdd(&g_arrive[b][gp], 1u);
                while (atomicAdd(&g_arrive[b][gp], 0u) < NSPLIT)
                    __nanosleep(64);
            }
            __syncthreads();

            // redundant selection: every block scans the merged histogram
            uint4 ha = *(const uint4*)&hist[8 * tid];
            uint4 hb = *(const uint4*)&hist[8 * tid + 4];
            unsigned hh[8] = {ha.x, ha.y, ha.z, ha.w, hb.x, hb.y, hb.z, hb.w};
            unsigned local = 0;
            #pragma unroll
            for (int j = 0; j < 8; j++) local += hh[j];
            unsigned incl = local;
            #pragma unroll
            for (int o = 1; o < 32; o <<= 1) {
                unsigned t = __shfl_up_sync(0xFFFFFFFFu, incl, o);
                if (lane >= o) incl += t;
            }
            if (lane == 31) s_wsum[w] = incl;
            __syncthreads();
            if (tid == 0) {
                unsigned run = 0;
                #pragma unroll
                for (int i = 0; i < 8; i++) {
                    unsigned t = s_wsum[i];
                    s_woff[i] = run;
                    run += t;
                }
            }
            __syncthreads();
            unsigned cum = s_woff[w] + (incl - local);
            #pragma unroll
            for (int j = 0; j < 8; j++) {
                if (kk >= cum && kk < cum + hh[j]) {
                    s_sel[0] = pref | ((unsigned)(8 * tid + j) << shift);
                    s_sel[1] = kk - cum;
                }
                cum += hh[j];
            }
            __syncthreads();
            pref = s_sel[0];
            kk   = s_sel[1];
            __syncthreads();
        }

        if (mode == 0) {
            // transform register keys in place: |med - y|
            const float med = kfloat(pref);
            #pragma unroll
            for (int j = 0; j < 8; j++)
                key[j] = fkey(fabsf(med - kfloat(key[j])));
        } else {
            if (split == 0 && tid == 0) g_thr[b] = kfloat(pref);
        }
    }
}

// ---------------------------------------------------------------------------
// Plane hypothesis (matches jnp.cross / norm / d = -n.p1)
// ---------------------------------------------------------------------------
__device__ __forceinline__ float4 compute_plane(const float4* __restrict__ prior,
                                                const int* __restrict__ sidx,
                                                int i) {
    int s0 = sidx[i * 3 + 0];
    int s1 = sidx[i * 3 + 1];
    int s2 = sidx[i * 3 + 2];
    float4 p1 = prior[s0];
    float4 p2 = prior[s1];
    float4 p3 = prior[s2];
    float ax = p2.x - p1.x, ay = p2.y - p1.y, az = p2.z - p1.z;
    float bx = p3.x - p1.x, by = p3.y - p1.y, bz = p3.z - p1.z;
    float nx = ay * bz - az * by;
    float ny = az * bx - ax * bz;
    float nz = ax * by - ay * bx;
    float norm = sqrtf(nx * nx + ny * ny + nz * nz);
    float inv = 1.0f / (norm + 1e-8f);
    nx *= inv; ny *= inv; nz *= inv;
    float d = -(nx * p1.x + ny * p1.y + nz * p1.z);
    return make_float4(nx, ny, nz, d);
}

// ---------------------------------------------------------------------------
// Kernel 3: RANSAC inlier counting + fused finalize (ticket pattern).
// grid = (25, 16), block = 256
// ---------------------------------------------------------------------------
__global__ void __launch_bounds__(256) ransac_kernel(const int* __restrict__ sidx,
                                                     float* __restrict__ out) {
    __shared__ float4 s_plane[NH];
    __shared__ unsigned s_cnt[NH];

    const int b   = blockIdx.y;
    const int tid = threadIdx.x;
    const int i0  = blockIdx.x * NH;

    const float4* __restrict__ prior = &g_prior[b * NPRIOR];

    if (tid < NH) {
        s_plane[tid] = compute_plane(prior, sidx, i0 + tid);
        s_cnt[tid] = 0u;
    }
    __syncthreads();

    const float thr = g_thr[b];
    float4 pl[NH];
    #pragma unroll
    for (int h = 0; h < NH; h++) pl[h] = s_plane[h];

    int cnt[NH];
    #pragma unroll
    for (int h = 0; h < NH; h++) cnt[h] = 0;

    #pragma unroll 2
    for (int n = tid; n < NPRIOR; n += 256) {
        float4 p = prior[n];
        #pragma unroll
        for (int h = 0; h < NH; h++) {
            float dist = fabsf(fmaf(pl[h].x, p.x,
                               fmaf(pl[h].y, p.y,
                               fmaf(pl[h].z, p.z, pl[h].w))));
            cnt[h] += (dist <= thr) ? 1 : 0;
        }
    }

    #pragma unroll
    for (int h = 0; h < NH; h++) {
        int c = __reduce_add_sync(0xFFFFFFFFu, cnt[h]);
        if ((tid & 31) == 0) atomicAdd(&s_cnt[h], (unsigned)c);
    }
    __syncthreads();

    if (tid < NH) {
        int i = i0 + tid;
        // argmax with first-index tie-break: larger count wins;
        // equal count -> larger (199-i) wins -> smaller i wins.
        unsigned key = (s_cnt[tid] << 8) | (unsigned)(ITERS - 1 - i);
        atomicMax(&g_best[b], key);
    }
    __syncthreads();

    // last-block finalize (canonical threadfence-reduction ticket pattern)
    if (tid == 0) {
        __threadfence();
        unsigned t = atomicAdd(&g_done[b], 1u);
        if (t == RNB - 1) {
            g_done[b] = 0u;                          // reset for graph replay
            unsigned best = atomicMax(&g_best[b], 0u);  // read with L2 visibility
            int i = ITERS - 1 - (int)(best & 0xFFu);
            float4 pw = compute_plane(prior, sidx, i);
            g_plane[b] = pw;
            out[b * 4 + 0] = pw.x;
            out[b * 4 + 1] = pw.y;
            out[b * 4 + 2] = pw.z;
            out[b * 4 + 3] = pw.w;
        }
    }
}

// ---------------------------------------------------------------------------
// Kernel 4: full-image inlier mask (0.0/1.0), 8 px/thread, pure streaming.
// Block = 256 threads covering 2048 pixels; 60 blocks/batch, 960 total.
// ---------------------------------------------------------------------------
__global__ void __launch_bounds__(256) mask_kernel(const float* __restrict__ pt,
                                                   float* __restrict__ out) {
    const int tid  = threadIdx.x;
    const int blk  = blockIdx.x;
    const int b    = blk / (HW / 2048);          // 60 blocks per batch
    const int mblk = (blk - b * (HW / 2048)) * 2048;

    const float4 pl  = g_plane[b];
    const float  thr = g_thr[b];

    const int m = mblk + tid * 8;                 // 8 pixels per thread
    const long base = (long)b * 3 * HW + m;

    float4 x0 = *(const float4*)(pt + base);
    float4 x1 = *(const float4*)(pt + base + 4);
    float4 y0 = *(const float4*)(pt + base + HW);
    float4 y1 = *(const float4*)(pt + base + HW + 4);
    float4 z0 = *(const float4*)(pt + base + 2 * HW);
    float4 z1 = *(const float4*)(pt + base + 2 * HW + 4);

    float4 r0, r1;
    r0.x = (fabsf(fmaf(pl.x, x0.x, fmaf(pl.y, y0.x, fmaf(pl.z, z0.x, pl.w)))) <= thr) ? 1.0f : 0.0f;
    r0.y = (fabsf(fmaf(pl.x, x0.y, fmaf(pl.y, y0.y, fmaf(pl.z, z0.y, pl.w)))) <= thr) ? 1.0f : 0.0f;
    r0.z = (fabsf(fmaf(pl.x, x0.z, fmaf(pl.y, y0.z, fmaf(pl.z, z0.z, pl.w)))) <= thr) ? 1.0f : 0.0f;
    r0.w = (fabsf(fmaf(pl.x, x0.w, fmaf(pl.y, y0.w, fmaf(pl.z, z0.w, pl.w)))) <= thr) ? 1.0f : 0.0f;
    r1.x = (fabsf(fmaf(pl.x, x1.x, fmaf(pl.y, y1.x, fmaf(pl.z, z1.x, pl.w)))) <= thr) ? 1.0f : 0.0f;
    r1.y = (fabsf(fmaf(pl.x, x1.y, fmaf(pl.y, y1.y, fmaf(pl.z, z1.y, pl.w)))) <= thr) ? 1.0f : 0.0f;
    r1.z = (fabsf(fmaf(pl.x, x1.z, fmaf(pl.y, y1.z, fmaf(pl.z, z1.z, pl.w)))) <= thr) ? 1.0f : 0.0f;
    r1.w = (fabsf(fmaf(pl.x, x1.w, fmaf(pl.y, y1.w, fmaf(pl.z, z1.w, pl.w)))) <= thr) ? 1.0f : 0.0f;

    float* dst = out + BATCH * 4 + (long)b * HW + m;
    *(float4*)(dst)     = r0;
    *(float4*)(dst + 4) = r1;
}

// ---------------------------------------------------------------------------
extern "C" void kernel_launch(void* const* d_in, const int* in_sizes, int n_in,
                              void* d_out, int out_size) {
    const float* pt   = (const float*)d_in[0];   // (B, 3, H*W)
    const float* Kmat = (const float*)d_in[1];   // (B, 3, 3)
    const int*   sidx = (const int*)d_in[2];     // (200, 3)
    float*       out  = (float*)d_out;           // [B*4 planes][B*H*W mask]

    {
        int total = BATCH * NPRIOR;
        pack_kernel<<<(total + 255) / 256, 256>>>(pt, Kmat);
    }
    {
        dim3 grid(NSPLIT, BATCH);                // (8, 16) co-resident
        median_kernel<<<grid, 256>>>();
    }
    {
        dim3 grid(RNB, BATCH);                   // (25, 16)
        ransac_kernel<<<grid, 256>>>(sidx, (float*)d_out);
    }
    {
        int blocks = BATCH * HW / 2048;          // 960
        mask_kernel<<<blocks, 256>>>(pt, out);
    }
}

// round 17
// speedup vs baseline: 1.2471x; 1.2471x over previous
#include <cuda_runtime.h>
#include <cuda_bf16.h>
#include <cstdint>

// Problem constants (fixed by setup_inputs)
#define BATCH   16
#define IMG_H   192
#define IMG_W   640
#define HW      (IMG_H * IMG_W)       // 122880
#define XS      240                   // W*3/8
#define XE      400                   // W*5/8
#define PRIOR_W (XE - XS)             // 160
#define NPRIOR  15360                 // (192-96)*160
#define ITERS   200
#define KMED    ((NPRIOR - 1) / 2)    // 7679, torch lower-median index
#define EPT     15                    // elements per thread (15360/1024)
#define NH      8                     // hypotheses per ransac block (fits regs)
#define RNB     (ITERS / NH)          // 25 ransac blocks per batch

// Scratch (static device globals — no allocation)
__device__ float4   g_prior[BATCH * NPRIOR];    // packed prior points (x,y,z,0)
__device__ float    g_prior_y[BATCH * NPRIOR];  // y channel contiguous
__device__ float    g_thr[BATCH];
__device__ unsigned g_best[BATCH];              // (count<<8) | (199-iter)
__device__ unsigned g_done[BATCH];              // ransac tickets (self-resetting)
__device__ float4   g_plane[BATCH];             // winning plane per batch

// ---------------------------------------------------------------------------
// order-preserving float <-> uint key
// ---------------------------------------------------------------------------
__device__ __forceinline__ unsigned fkey(float f) {
    unsigned u = __float_as_uint(f);
    return (u & 0x80000000u) ? ~u : (u | 0x80000000u);
}
__device__ __forceinline__ float kfloat(unsigned k) {
    unsigned u = (k & 0x80000000u) ? (k ^ 0x80000000u) : ~k;
    return __uint_as_float(u);
}

// ---------------------------------------------------------------------------
// Kernel 1: pack prior crop into contiguous buffers; init g_best
// ---------------------------------------------------------------------------
__global__ void pack_kernel(const float* __restrict__ pt,
                            const float* __restrict__ Kmat) {
    int idx = blockIdx.x * blockDim.x + threadIdx.x;
    if (idx < BATCH) g_best[idx] = 0u;
    if (idx >= BATCH * NPRIOR) return;
    int b = idx / NPRIOR;
    int n = idx - b * NPRIOR;
    int ys = (int)Kmat[b * 9 + 5];            // K[b,1,2] -> 96
    int r = n / PRIOR_W;
    int c = n - r * PRIOR_W;
    long base = (long)b * 3 * HW + (long)(ys + r) * IMG_W + XS + c;
    float x = pt[base];
    float y = pt[base + HW];
    float z = pt[base + 2 * HW];
    g_prior[idx]   = make_float4(x, y, z, 0.0f);
    g_prior_y[idx] = y;
}

// ---------------------------------------------------------------------------
// Kernel 2: exact lower-median via 3-pass (11/11/10-bit) radix select, twice:
//   med = median_low(y);  thr = median_low(|med - y|)
// One block per batch, 1024 threads. KEYS REGISTER-RESIDENT (15/thread):
// per element per pass only shift+predicate+ATOMS (~3 instr), no smem
// staging loads, no per-pass fkey recompute. 2048-bin smem histogram with
// parallel block-scan bin selection (validated). Digit layout: bits
// [21:32), [10:21), [0:10); pass filter compares bits >= HI[pass].
// ---------------------------------------------------------------------------
__global__ void __launch_bounds__(1024) median_kernel() {
    __shared__ unsigned s_hist[2048];      // 8 KB
    __shared__ unsigned s_wsum[32];
    __shared__ unsigned s_woff[32];
    __shared__ unsigned s_prefix;
    __shared__ unsigned s_k;
    __shared__ float    s_med;

    const int b    = blockIdx.x;
    const int tid  = threadIdx.x;
    const int lane = tid & 31;
    const int w    = tid >> 5;

    // load keys into registers once (coalesced; exactly 15 per thread)
    unsigned k[EPT];
    {
        const float* __restrict__ yv = &g_prior_y[b * NPRIOR];
        #pragma unroll
        for (int j = 0; j < EPT; j++)
            k[j] = fkey(yv[tid + j * 1024]);
    }

    const int SHIFT[3]      = {21, 10, 0};     // digit start bit
    const unsigned DMASK[3] = {0x7FFu, 0x7FFu, 0x3FFu};
    const int HI[3]         = {32, 21, 10};    // resolved-prefix boundary

    for (int mode = 0; mode < 2; mode++) {
        if (tid == 0) { s_prefix = 0u; s_k = KMED; }
        __syncthreads();

        for (int pass = 0; pass < 3; pass++) {
            const int shift = SHIFT[pass];
            const unsigned dmask = DMASK[pass];
            const int hi = HI[pass];
            // zero histogram (2 bins per thread)
            s_hist[tid]        = 0u;
            s_hist[tid + 1024] = 0u;
            __syncthreads();
            const unsigned pref = s_prefix;
            const unsigned kk   = s_k;

            // histogram register keys matching the resolved prefix
            if (pass == 0) {
                #pragma unroll
                for (int j = 0; j < EPT; j++)
                    atomicAdd(&s_hist[(k[j] >> shift) & dmask], 1u);
            } else {
                const unsigned ph = pref >> hi;
                #pragma unroll
                for (int j = 0; j < EPT; j++)
                    if ((k[j] >> hi) == ph)
                        atomicAdd(&s_hist[(k[j] >> shift) & dmask], 1u);
            }
            __syncthreads();

            // parallel exclusive scan over 2048 bins (2 contiguous per thread)
            unsigned h0 = s_hist[2 * tid];
            unsigned h1 = s_hist[2 * tid + 1];
            unsigned local = h0 + h1;
            unsigned incl = local;
            #pragma unroll
            for (int o = 1; o < 32; o <<= 1) {
                unsigned v = __shfl_up_sync(0xFFFFFFFFu, incl, o);
                if (lane >= o) incl += v;
            }
            if (lane == 31) s_wsum[w] = incl;
            __syncthreads();
            if (w == 0) {
                unsigned v = s_wsum[lane];
                unsigned s = v;
                #pragma unroll
                for (int o = 1; o < 32; o <<= 1) {
                    unsigned t = __shfl_up_sync(0xFFFFFFFFu, s, o);
                    if (lane >= o) s += t;
                }
                s_woff[lane] = s - v;   // exclusive warp offset
            }
            __syncthreads();
            unsigned excl = s_woff[w] + (incl - local);
            unsigned cum0 = excl;
            unsigned cum1 = excl + h0;
            if (kk >= cum0 && kk < cum0 + h0) {
                s_prefix = pref | ((unsigned)(2 * tid) << shift);
                s_k = kk - cum0;
            }
            if (kk >= cum1 && kk < cum1 + h1) {
                s_prefix = pref | ((unsigned)(2 * tid + 1) << shift);
                s_k = kk - cum1;
            }
            __syncthreads();
        }

        if (mode == 0) {
            if (tid == 0) s_med = kfloat(s_prefix);
            __syncthreads();
            // transform register keys in place: |med - y| (validated in R14)
            const float med = s_med;
            #pragma unroll
            for (int j = 0; j < EPT; j++)
                k[j] = fkey(fabsf(med - kfloat(k[j])));
        } else {
            if (tid == 0) g_thr[b] = kfloat(s_prefix);
        }
    }
}

// ---------------------------------------------------------------------------
// Plane hypothesis (matches jnp.cross / norm / d = -n.p1)
// ---------------------------------------------------------------------------
__device__ __forceinline__ float4 compute_plane(const float4* __restrict__ prior,
                                                const int* __restrict__ sidx,
                                                int i) {
    int s0 = sidx[i * 3 + 0];
    int s1 = sidx[i * 3 + 1];
    int s2 = sidx[i * 3 + 2];
    float4 p1 = prior[s0];
    float4 p2 = prior[s1];
    float4 p3 = prior[s2];
    float ax = p2.x - p1.x, ay = p2.y - p1.y, az = p2.z - p1.z;
    float bx = p3.x - p1.x, by = p3.y - p1.y, bz = p3.z - p1.z;
    float nx = ay * bz - az * by;
    float ny = az * bx - ax * bz;
    float nz = ax * by - ay * bx;
    float norm = sqrtf(nx * nx + ny * ny + nz * nz);
    float inv = 1.0f / (norm + 1e-8f);
    nx *= inv; ny *= inv; nz *= inv;
    float d = -(nx * p1.x + ny * p1.y + nz * p1.z);
    return make_float4(nx, ny, nz, d);
}

// ---------------------------------------------------------------------------
// Kernel 3: RANSAC inlier counting + fused finalize (ticket pattern).
// One block = NH(8) hypotheses sharing a single streaming pass over the
// points. The LAST block per batch resolves the argmax winner and writes
// g_plane[b] + the output plane head.  grid = (25, 16), block = 256
// ---------------------------------------------------------------------------
__global__ void __launch_bounds__(256) ransac_kernel(const int* __restrict__ sidx,
                                                     float* __restrict__ out) {
    __shared__ float4 s_plane[NH];
    __shared__ unsigned s_cnt[NH];

    const int b   = blockIdx.y;
    const int tid = threadIdx.x;
    const int i0  = blockIdx.x * NH;

    const float4* __restrict__ prior = &g_prior[b * NPRIOR];

    if (tid < NH) {
        s_plane[tid] = compute_plane(prior, sidx, i0 + tid);
        s_cnt[tid] = 0u;
    }
    __syncthreads();

    const float thr = g_thr[b];
    float4 pl[NH];
    #pragma unroll
    for (int h = 0; h < NH; h++) pl[h] = s_plane[h];

    int cnt[NH];
    #pragma unroll
    for (int h = 0; h < NH; h++) cnt[h] = 0;

    #pragma unroll 2
    for (int n = tid; n < NPRIOR; n += 256) {
        float4 p = prior[n];
        #pragma unroll
        for (int h = 0; h < NH; h++) {
            float dist = fabsf(fmaf(pl[h].x, p.x,
                               fmaf(pl[h].y, p.y,
                               fmaf(pl[h].z, p.z, pl[h].w))));
            cnt[h] += (dist <= thr) ? 1 : 0;
        }
    }

    #pragma unroll
    for (int h = 0; h < NH; h++) {
        int c = __reduce_add_sync(0xFFFFFFFFu, cnt[h]);
        if ((tid & 31) == 0) atomicAdd(&s_cnt[h], (unsigned)c);
    }
    __syncthreads();

    if (tid < NH) {
        int i = i0 + tid;
        // argmax with first-index tie-break: larger count wins;
        // equal count -> larger (199-i) wins -> smaller i wins.
        unsigned key = (s_cnt[tid] << 8) | (unsigned)(ITERS - 1 - i);
        atomicMax(&g_best[b], key);
    }
    __syncthreads();

    // last-block finalize (canonical threadfence-reduction ticket pattern)
    if (tid == 0) {
        __threadfence();
        unsigned t = atomicAdd(&g_done[b], 1u);
        if (t == RNB - 1) {
            g_done[b] = 0u;                          // reset for graph replay
            unsigned best = atomicMax(&g_best[b], 0u);  // read with L2 visibility
            int i = ITERS - 1 - (int)(best & 0xFFu);
            float4 pw = compute_plane(prior, sidx, i);
            g_plane[b] = pw;
            out[b * 4 + 0] = pw.x;
            out[b * 4 + 1] = pw.y;
            out[b * 4 + 2] = pw.z;
            out[b * 4 + 3] = pw.w;
        }
    }
}

// ---------------------------------------------------------------------------
// Kernel 4: full-image inlier mask (0.0/1.0), 8 px/thread, pure streaming:
// plane/thr read per-thread from g_plane/g_thr (L2 broadcast), no smem,
// no syncthreads, no serial block head.
// Block = 256 threads covering 2048 pixels; 60 blocks/batch, 960 total.
// ---------------------------------------------------------------------------
__global__ void __launch_bounds__(256) mask_kernel(const float* __restrict__ pt,
                                                   float* __restrict__ out) {
    const int tid  = threadIdx.x;
    const int blk  = blockIdx.x;
    const int b    = blk / (HW / 2048);          // 60 blocks per batch
    const int mblk = (blk - b * (HW / 2048)) * 2048;

    const float4 pl  = g_plane[b];
    const float  thr = g_thr[b];

    const int m = mblk + tid * 8;                 // 8 pixels per thread
    const long base = (long)b * 3 * HW + m;

    float4 x0 = *(const float4*)(pt + base);
    float4 x1 = *(const float4*)(pt + base + 4);
    float4 y0 = *(const float4*)(pt + base + HW);
    float4 y1 = *(const float4*)(pt + base + HW + 4);
    float4 z0 = *(const float4*)(pt + base + 2 * HW);
    float4 z1 = *(const float4*)(pt + base + 2 * HW + 4);

    float4 r0, r1;
    r0.x = (fabsf(fmaf(pl.x, x0.x, fmaf(pl.y, y0.x, fmaf(pl.z, z0.x, pl.w)))) <= thr) ? 1.0f : 0.0f;
    r0.y = (fabsf(fmaf(pl.x, x0.y, fmaf(pl.y, y0.y, fmaf(pl.z, z0.y, pl.w)))) <= thr) ? 1.0f : 0.0f;
    r0.z = (fabsf(fmaf(pl.x, x0.z, fmaf(pl.y, y0.z, fmaf(pl.z, z0.z, pl.w)))) <= thr) ? 1.0f : 0.0f;
    r0.w = (fabsf(fmaf(pl.x, x0.w, fmaf(pl.y, y0.w, fmaf(pl.z, z0.w, pl.w)))) <= thr) ? 1.0f : 0.0f;
    r1.x = (fabsf(fmaf(pl.x, x1.x, fmaf(pl.y, y1.x, fmaf(pl.z, z1.x, pl.w)))) <= thr) ? 1.0f : 0.0f;
    r1.y = (fabsf(fmaf(pl.x, x1.y, fmaf(pl.y, y1.y, fmaf(pl.z, z1.y, pl.w)))) <= thr) ? 1.0f : 0.0f;
    r1.z = (fabsf(fmaf(pl.x, x1.z, fmaf(pl.y, y1.z, fmaf(pl.z, z1.z, pl.w)))) <= thr) ? 1.0f : 0.0f;
    r1.w = (fabsf(fmaf(pl.x, x1.w, fmaf(pl.y, y1.w, fmaf(pl.z, z1.w, pl.w)))) <= thr) ? 1.0f : 0.0f;

    float* dst = out + BATCH * 4 + (long)b * HW + m;
    *(float4*)(dst)     = r0;
    *(float4*)(dst + 4) = r1;
}

// ---------------------------------------------------------------------------
extern "C" void kernel_launch(void* const* d_in, const int* in_sizes, int n_in,
                              void* d_out, int out_size) {
    const float* pt   = (const float*)d_in[0];   // (B, 3, H*W)
    const float* Kmat = (const float*)d_in[1];   // (B, 3, 3)
    const int*   sidx = (const int*)d_in[2];     // (200, 3)
    float*       out  = (float*)d_out;           // [B*4 planes][B*H*W mask]

    {
        int total = BATCH * NPRIOR;
        pack_kernel<<<(total + 255) / 256, 256>>>(pt, Kmat);
    }
    median_kernel<<<BATCH, 1024>>>();
    {
        dim3 grid(RNB, BATCH);                   // (25, 16)
        ransac_kernel<<<grid, 256>>>(sidx, (float*)d_out);
    }
    {
        int blocks = BATCH * HW / 2048;          // 960
        mask_kernel<<<blocks, 256>>>(pt, out);
    }
}